// round 5
// baseline (speedup 1.0000x reference)
#include <cuda_runtime.h>
#include <cstdint>

#define BB 512
#define NN 16384
#define H2 (0.0078125f * 0.0078125f)
#define THREADS 256
#define NWARP (THREADS / 32)
#define SPLIT 4
#define ITERS 4                         // chunks per slice (1024 groups / 256 threads)
#define STAGES 3
#define CHUNK_BYTES 36864               // 5*4096 + 16384
#define OFF_P(j) (4096 * (1 + (j)))
#define OFF_T 20480
#define MBAR_OFF (STAGES * CHUNK_BYTES) // barriers after the 3 stages
#define SMEM_BYTES (MBAR_OFF + 64)

__device__ float g_part[BB * SPLIT * 26];
__device__ float g_per_sample[BB];
__device__ unsigned int g_batch_cnt[BB];
__device__ unsigned int g_done_count = 0;

__device__ __forceinline__ uint32_t smem_u32(const void* p) {
    uint32_t a;
    asm("{ .reg .u64 t; cvta.to.shared.u64 t, %1; cvt.u32.u64 %0, t; }" : "=r"(a) : "l"(p));
    return a;
}
__device__ __forceinline__ void mbar_init(uint32_t mb, uint32_t cnt) {
    asm volatile("mbarrier.init.shared.b64 [%0], %1;" :: "r"(mb), "r"(cnt) : "memory");
}
__device__ __forceinline__ void mbar_expect_tx(uint32_t mb, uint32_t bytes) {
    asm volatile("mbarrier.arrive.expect_tx.shared.b64 _, [%0], %1;" :: "r"(mb), "r"(bytes) : "memory");
}
__device__ __forceinline__ void mbar_wait(uint32_t mb, uint32_t parity) {
    asm volatile(
        "{\n\t.reg .pred P;\n\t"
        "WL_%=:\n\t"
        "mbarrier.try_wait.parity.acquire.cta.shared::cta.b64 P, [%0], %1, 0x989680;\n\t"
        "@P bra.uni WD_%=;\n\t"
        "bra.uni WL_%=;\n\t"
        "WD_%=:\n\t}"
        :: "r"(mb), "r"(parity) : "memory");
}
__device__ __forceinline__ void bulk_g2s(uint32_t dst, const void* src, uint32_t bytes, uint32_t mb) {
    asm volatile(
        "cp.async.bulk.shared::cta.global.mbarrier::complete_tx::bytes [%0], [%1], %2, [%3];"
        :: "r"(dst), "l"(src), "r"(bytes), "r"(mb) : "memory");
}

#define LANE(cc, P0, P1, P2, P3, TT) do {                                   \
    float a_  = H2 * (cc);                                                  \
    float ap0 = a_ * (P0), ap1 = a_ * (P1), ap2 = a_ * (P2), ap3 = a_ * (P3); \
    G[0] += ap0 * (P0);                                                     \
    G[1] += ap1 * (P0); G[2] += ap1 * (P1);                                 \
    G[3] += ap2 * (P0); G[4] += ap2 * (P1); G[5] += ap2 * (P2);             \
    G[6] += ap3 * (P0); G[7] += ap3 * (P1); G[8] += ap3 * (P2); G[9] += ap3 * (P3); \
    T[ 0] += ap0 * TT.x; T[ 1] += ap0 * TT.y; T[ 2] += ap0 * TT.z; T[ 3] += ap0 * TT.w; \
    T[ 4] += ap1 * TT.x; T[ 5] += ap1 * TT.y; T[ 6] += ap1 * TT.z; T[ 7] += ap1 * TT.w; \
    T[ 8] += ap2 * TT.x; T[ 9] += ap2 * TT.y; T[10] += ap2 * TT.z; T[11] += ap2 * TT.w; \
    T[12] += ap3 * TT.x; T[13] += ap3 * TT.y; T[14] += ap3 * TT.z; T[15] += ap3 * TT.w; \
} while (0)

__global__ __launch_bounds__(THREADS)
void loss_pipe_kernel(const float* __restrict__ coef,
                      const float* __restrict__ preds,
                      const float* __restrict__ targs,
                      float* __restrict__ out)
{
    extern __shared__ char smem[];
    const uint32_t smem_base = smem_u32(smem);
    const uint32_t mbar_base = smem_base + MBAR_OFF;

    const int blk = blockIdx.x;
    const int b = blk >> 2;
    const int s = blk & (SPLIT - 1);
    const int tid = threadIdx.x;

    const float* cb = coef  + (size_t)b * NN;
    const float* pb = preds + (size_t)b * 4 * NN;
    const float* tb = targs + (size_t)b * NN * 4;

    // ---- producer: init barriers, prefetch STAGES chunks (tid 0 only) ----
    if (tid == 0) {
#pragma unroll
        for (int st = 0; st < STAGES; st++) mbar_init(mbar_base + st * 8, 1);
        asm volatile("fence.proxy.async.shared::cta;" ::: "memory");
#pragma unroll
        for (int st = 0; st < STAGES; st++) {
            const int n4b = s * 1024 + st * 256;        // float4-group base of chunk
            const uint32_t mb  = mbar_base + st * 8;
            const uint32_t dst = smem_base + st * CHUNK_BYTES;
            mbar_expect_tx(mb, CHUNK_BYTES);
            bulk_g2s(dst,            cb + n4b * 4,          4096,  mb);
            bulk_g2s(dst + OFF_P(0), pb + 0 * NN + n4b * 4, 4096,  mb);
            bulk_g2s(dst + OFF_P(1), pb + 1 * NN + n4b * 4, 4096,  mb);
            bulk_g2s(dst + OFF_P(2), pb + 2 * NN + n4b * 4, 4096,  mb);
            bulk_g2s(dst + OFF_P(3), pb + 3 * NN + n4b * 4, 4096,  mb);
            bulk_g2s(dst + OFF_T,    tb + n4b * 16,         16384, mb);
        }
    }
    __syncthreads();

    float G[10], T[16];
#pragma unroll
    for (int i = 0; i < 10; i++) G[i] = 0.f;
#pragma unroll
    for (int i = 0; i < 16; i++) T[i] = 0.f;

#pragma unroll
    for (int k = 0; k < ITERS; k++) {
        const int st = k % STAGES;
        mbar_wait(mbar_base + st * 8, (k / STAGES) & 1);

        const char* stg = smem + st * CHUNK_BYTES;
        float4 cv = *(const float4*)(stg +            tid * 16);
        float4 a0 = *(const float4*)(stg + OFF_P(0) + tid * 16);
        float4 a1 = *(const float4*)(stg + OFF_P(1) + tid * 16);
        float4 a2 = *(const float4*)(stg + OFF_P(2) + tid * 16);
        float4 a3 = *(const float4*)(stg + OFF_P(3) + tid * 16);
        float4 t0 = *(const float4*)(stg + OFF_T + tid * 64 +  0);
        float4 t1 = *(const float4*)(stg + OFF_T + tid * 64 + 16);
        float4 t2 = *(const float4*)(stg + OFF_T + tid * 64 + 32);
        float4 t3 = *(const float4*)(stg + OFF_T + tid * 64 + 48);

        LANE(cv.x, a0.x, a1.x, a2.x, a3.x, t0);
        LANE(cv.y, a0.y, a1.y, a2.y, a3.y, t1);
        LANE(cv.z, a0.z, a1.z, a2.z, a3.z, t2);
        LANE(cv.w, a0.w, a1.w, a2.w, a3.w, t3);

        // reuse this stage for chunk k+STAGES (only k==0 with ITERS=4, STAGES=3)
        if (k + STAGES < ITERS) {
            __syncthreads();   // all threads finished reading stage st
            if (tid == 0) {
                const int kk = k + STAGES;
                const int n4b = s * 1024 + kk * 256;
                const uint32_t mb  = mbar_base + st * 8;
                const uint32_t dst = smem_base + st * CHUNK_BYTES;
                mbar_expect_tx(mb, CHUNK_BYTES);
                bulk_g2s(dst,            cb + n4b * 4,          4096,  mb);
                bulk_g2s(dst + OFF_P(0), pb + 0 * NN + n4b * 4, 4096,  mb);
                bulk_g2s(dst + OFF_P(1), pb + 1 * NN + n4b * 4, 4096,  mb);
                bulk_g2s(dst + OFF_P(2), pb + 2 * NN + n4b * 4, 4096,  mb);
                bulk_g2s(dst + OFF_P(3), pb + 3 * NN + n4b * 4, 4096,  mb);
                bulk_g2s(dst + OFF_T,    tb + n4b * 16,         16384, mb);
            }
        }
    }

    // ---- warp reduce 26 accumulators ----
#pragma unroll
    for (int i = 0; i < 10; i++) {
#pragma unroll
        for (int off = 16; off > 0; off >>= 1)
            G[i] += __shfl_down_sync(0xFFFFFFFFu, G[i], off);
    }
#pragma unroll
    for (int i = 0; i < 16; i++) {
#pragma unroll
        for (int off = 16; off > 0; off >>= 1)
            T[i] += __shfl_down_sync(0xFFFFFFFFu, T[i], off);
    }

    // reuse stage 0 smem for the cross-warp reduction
    float (*sred)[NWARP] = (float (*)[NWARP])smem;
    __syncthreads();                     // everyone done with pipeline smem
    const int lid = tid & 31;
    const int wid = tid >> 5;
    if (lid == 0) {
#pragma unroll
        for (int i = 0; i < 10; i++) sred[i][wid] = G[i];
#pragma unroll
        for (int i = 0; i < 16; i++) sred[10 + i][wid] = T[i];
    }
    __syncthreads();

    if (tid < 26) {
        float v = 0.f;
#pragma unroll
        for (int w = 0; w < NWARP; w++) v += sred[tid][w];
        g_part[(size_t)blk * 26 + tid] = v;
    }

    __shared__ bool s_batch_last, s_global_last;
    if (tid == 0) s_global_last = false;
    __threadfence();
    __syncthreads();
    if (tid == 0) {
        unsigned int prev = atomicInc(&g_batch_cnt[b], SPLIT - 1);
        s_batch_last = (prev == SPLIT - 1);
    }
    __syncthreads();

    if (s_batch_last && tid == 0) {
        float Gs[10], Ts[16];
        {
            float acc[26];
#pragma unroll
            for (int i = 0; i < 26; i++) acc[i] = 0.f;
            const float* pp = &g_part[(size_t)(b * SPLIT) * 26];
#pragma unroll
            for (int sl = 0; sl < SPLIT; sl++)
#pragma unroll
                for (int i = 0; i < 26; i++)
                    acc[i] += __ldcg(pp + sl * 26 + i);
#pragma unroll
            for (int i = 0; i < 10; i++) Gs[i] = acc[i];
#pragma unroll
            for (int i = 0; i < 16; i++) Ts[i] = acc[10 + i];
        }

        float Gm[4][4];
        Gm[0][0] = Gs[0];
        Gm[1][0] = Gm[0][1] = Gs[1]; Gm[1][1] = Gs[2];
        Gm[2][0] = Gm[0][2] = Gs[3]; Gm[2][1] = Gm[1][2] = Gs[4]; Gm[2][2] = Gs[5];
        Gm[3][0] = Gm[0][3] = Gs[6]; Gm[3][1] = Gm[1][3] = Gs[7];
        Gm[3][2] = Gm[2][3] = Gs[8]; Gm[3][3] = Gs[9];

        float L[4][4];
#pragma unroll
        for (int j = 0; j < 4; j++) {
            float v[4] = {0.f, 0.f, 0.f, 0.f};
            v[j] = 1.f;
#pragma unroll
            for (int e = 0; e < 4; e++) {
                if (e >= j) break;
                float proj = 0.f;
#pragma unroll
                for (int k = 0; k < 4; k++) {
                    float gv = 0.f;
#pragma unroll
                    for (int l = 0; l < 4; l++) gv += Gm[k][l] * L[e][l];
                    proj += v[k] * gv;
                }
#pragma unroll
                for (int k = 0; k < 4; k++) v[k] -= proj * L[e][k];
            }
            float n2 = 0.f;
#pragma unroll
            for (int k = 0; k < 4; k++) {
                float gv = 0.f;
#pragma unroll
                for (int l = 0; l < 4; l++) gv += Gm[k][l] * v[l];
                n2 += v[k] * gv;
            }
            float sc = (n2 > 0.f) ? rsqrtf(n2) : 1.f;
#pragma unroll
            for (int k = 0; k < 4; k++) L[j][k] = v[k] * sc;
        }

        float ss = 0.f;
#pragma unroll
        for (int j = 0; j < 4; j++) {
#pragma unroll
            for (int m = 0; m < 4; m++) {
                float mv = 0.f;
#pragma unroll
                for (int k = 0; k < 4; k++) mv += L[j][k] * Ts[k * 4 + m];
                ss += mv * mv;
            }
        }
        g_per_sample[b] = (4.f - ss) * 0.25f;

        __threadfence();
        unsigned int prev = atomicInc(&g_done_count, BB - 1);
        s_global_last = (prev == BB - 1);
    }
    __syncthreads();

    if (s_global_last) {
        float* sfin = (float*)smem;
        float v = __ldcg(&g_per_sample[tid]) + __ldcg(&g_per_sample[tid + THREADS]);
        sfin[tid] = v;
        __syncthreads();
#pragma unroll
        for (int off = THREADS / 2; off > 0; off >>= 1) {
            if (tid < off) sfin[tid] += sfin[tid + off];
            __syncthreads();
        }
        if (tid == 0) out[0] = sfin[0] * (1.f / (float)BB);
    }
}

extern "C" void kernel_launch(void* const* d_in, const int* in_sizes, int n_in,
                              void* d_out, int out_size)
{
    const float* coef  = (const float*)d_in[0];
    const float* preds = (const float*)d_in[1];
    const float* targs = (const float*)d_in[2];
    float* out = (float*)d_out;

    cudaFuncSetAttribute(loss_pipe_kernel,
                         cudaFuncAttributeMaxDynamicSharedMemorySize, SMEM_BYTES);
    loss_pipe_kernel<<<BB * SPLIT, THREADS, SMEM_BYTES>>>(coef, preds, targs, out);
}